// round 1
// baseline (speedup 1.0000x reference)
#include <cuda_runtime.h>
#include <cuda_bf16.h>

// Problem constants (from reference)
#define NBLK 33
#define NOPS 19
#define Dm   128
#define Hf   512
#define Bb   8
#define Ss   1024
#define MT   (Bb * Ss)   // 8192 total rows

// ---------------------------------------------------------------------------
// Device scratch (static global allocation; no runtime alloc)
// ---------------------------------------------------------------------------
__device__ int   g_flags[3];           // [op, do_attn, do_ffn]
__device__ float g_q [MT * Dm];
__device__ float g_k [MT * Dm];
__device__ float g_v [MT * Dm];
__device__ float g_ao[MT * Dm];        // attention output (pre-Wo)
__device__ float g_p [(size_t)Bb * Ss * Ss];  // scores / probabilities (32 MB)
__device__ float g_z [MT * Hf];        // FFN hidden

// ---------------------------------------------------------------------------
// Hardcoded routing masks (deterministic _build_masks() logic)
// ---------------------------------------------------------------------------
__device__ __forceinline__ bool is_carry(int op) {
    return op == 0 || op == 1 || op == 2 || (op >= 10 && op <= 13);
}
__device__ __forceinline__ bool amask(int blk, int op) {
    if (blk >= 1 && blk <= 7) return is_carry(op);
    if (blk == 8)             return op == 14 || op == 15 || op == 8 || op == 9;
    if (blk == 32)            return op >= 10 && op <= 13;
    return false;
}
__device__ __forceinline__ bool fmask(int blk, int op) {
    if (blk == 0)              return true;
    if (blk >= 1 && blk <= 7)  return is_carry(op);
    if (blk == 8)              return op == 14 || op == 15 || op == 8 || op == 9;
    if (blk >= 16 && blk <= 31) return op == 3 || op == 4;
    if (blk == 32)             return op == 5 || op == 6 || op == 7 || op == 2 ||
                                      op == 4 || (op >= 10 && op <= 13);
    return false;
}

// ---------------------------------------------------------------------------
// Per-block opcode + routing flags (1 thread; h[0,0,:NOPS] argmax, first max)
// ---------------------------------------------------------------------------
__global__ void k_op(const float* __restrict__ h, int blk) {
    float best = h[0];
    int   bi   = 0;
    for (int i = 1; i < NOPS; i++) {
        float v = h[i];
        if (v > best) { best = v; bi = i; }
    }
    g_flags[0] = bi;
    g_flags[1] = amask(blk, bi) ? 1 : 0;
    g_flags[2] = fmask(blk, bi) ? 1 : 0;
}

// ---------------------------------------------------------------------------
// Shared 64x64 fp32 GEMM tile body. 256 threads, 4x4 per thread, BK=16.
// A: row-major [64 x K] slab starting at `A` with leading dim lda.
// TRANSB=false: B is [K x N] row-major slab at `Bm` (col-offset already applied), ldb.
// TRANSB=true : B is [64 x K] row-major slab at `Bm` (row-offset applied), ldb -> C = A*B^T.
// ---------------------------------------------------------------------------
template <bool TRANSB>
__device__ __forceinline__ void gemm_tile(const float* __restrict__ A,
                                          const float* __restrict__ Bm,
                                          float (&acc)[4][4],
                                          int K, int lda, int ldb)
{
    __shared__ float Ast[16][64];
    __shared__ float Bst[16][64];

    const int tid = threadIdx.x;
    const int tx  = tid & 15;       // 0..15
    const int ty  = tid >> 4;       // 0..15
    const int lr  = tid >> 2;       // 0..63  (row for transposed loads)
    const int lc  = (tid & 3) * 4;  // 0,4,8,12
    const int br  = tid >> 4;       // 0..15  (k-row for NN B loads)
    const int bc  = (tid & 15) * 4; // 0..60

    for (int k0 = 0; k0 < K; k0 += 16) {
        float4 a4 = *(const float4*)(A + (size_t)lr * lda + k0 + lc);
        float4 b4;
        if (TRANSB) b4 = *(const float4*)(Bm + (size_t)lr * ldb + k0 + lc);
        else        b4 = *(const float4*)(Bm + (size_t)(k0 + br) * ldb + bc);

        __syncthreads();   // protect previous iteration's reads
        Ast[lc + 0][lr] = a4.x; Ast[lc + 1][lr] = a4.y;
        Ast[lc + 2][lr] = a4.z; Ast[lc + 3][lr] = a4.w;
        if (TRANSB) {
            Bst[lc + 0][lr] = b4.x; Bst[lc + 1][lr] = b4.y;
            Bst[lc + 2][lr] = b4.z; Bst[lc + 3][lr] = b4.w;
        } else {
            *(float4*)&Bst[br][bc] = b4;
        }
        __syncthreads();

#pragma unroll
        for (int k = 0; k < 16; k++) {
            float4 av = *(const float4*)&Ast[k][ty * 4];
            float4 bv = *(const float4*)&Bst[k][tx * 4];
            acc[0][0] += av.x * bv.x; acc[0][1] += av.x * bv.y;
            acc[0][2] += av.x * bv.z; acc[0][3] += av.x * bv.w;
            acc[1][0] += av.y * bv.x; acc[1][1] += av.y * bv.y;
            acc[1][2] += av.y * bv.z; acc[1][3] += av.y * bv.w;
            acc[2][0] += av.z * bv.x; acc[2][1] += av.z * bv.y;
            acc[2][2] += av.z * bv.z; acc[2][3] += av.z * bv.w;
            acc[3][0] += av.w * bv.x; acc[3][1] += av.w * bv.y;
            acc[3][2] += av.w * bv.z; acc[3][3] += av.w * bv.w;
        }
    }
}

// ---------------------------------------------------------------------------
// Q/K/V projection: grid (Dm/64, MT/64, 3).  out = h @ W[blk][op]
// ---------------------------------------------------------------------------
__global__ void k_qkv(const float* __restrict__ h,
                      const float* __restrict__ wq,
                      const float* __restrict__ wk,
                      const float* __restrict__ wv, int blk)
{
    if (!g_flags[1]) return;
    const int op = g_flags[0];
    const float* W = (blockIdx.z == 0) ? wq : (blockIdx.z == 1) ? wk : wv;
    W += ((size_t)blk * NOPS + op) * Dm * Dm;
    float* out = (blockIdx.z == 0) ? g_q : (blockIdx.z == 1) ? g_k : g_v;

    const float* A  = h + (size_t)blockIdx.y * 64 * Dm;
    const float* Bm = W + blockIdx.x * 64;

    float acc[4][4] = {};
    gemm_tile<false>(A, Bm, acc, Dm, Dm, Dm);

    const int row = blockIdx.y * 64 + (threadIdx.x >> 4) * 4;
    const int col = blockIdx.x * 64 + (threadIdx.x & 15) * 4;
#pragma unroll
    for (int i = 0; i < 4; i++)
#pragma unroll
        for (int j = 0; j < 4; j++)
            out[(size_t)(row + i) * Dm + col + j] = acc[i][j];
}

// ---------------------------------------------------------------------------
// Scores: grid (Ss/64, Ss/64, Bb).  P[b] = (Q[b] @ K[b]^T) * scale
// ---------------------------------------------------------------------------
__global__ void k_scores()
{
    if (!g_flags[1]) return;
    const float scale = 0.08838834764831845f;  // 1/sqrt(128)
    const float* A  = g_q + ((size_t)blockIdx.z * Ss + blockIdx.y * 64) * Dm;
    const float* Bm = g_k + ((size_t)blockIdx.z * Ss + blockIdx.x * 64) * Dm;
    float*       C  = g_p + (size_t)blockIdx.z * Ss * Ss;

    float acc[4][4] = {};
    gemm_tile<true>(A, Bm, acc, Dm, Dm, Dm);

    const int row = blockIdx.y * 64 + (threadIdx.x >> 4) * 4;
    const int col = blockIdx.x * 64 + (threadIdx.x & 15) * 4;
#pragma unroll
    for (int i = 0; i < 4; i++)
#pragma unroll
        for (int j = 0; j < 4; j++)
            C[(size_t)(row + i) * Ss + col + j] = acc[i][j] * scale;
}

// ---------------------------------------------------------------------------
// Row softmax over 1024 cols: grid MT (=B*S rows), 256 threads
// ---------------------------------------------------------------------------
__global__ void k_softmax()
{
    if (!g_flags[1]) return;
    __shared__ float red[256];
    float* p = g_p + (size_t)blockIdx.x * Ss;
    const int t = threadIdx.x;

    float v[4];
    float mx = -3.4e38f;
#pragma unroll
    for (int i = 0; i < 4; i++) { v[i] = p[t + i * 256]; mx = fmaxf(mx, v[i]); }
    red[t] = mx; __syncthreads();
    for (int s = 128; s > 0; s >>= 1) {
        if (t < s) red[t] = fmaxf(red[t], red[t + s]);
        __syncthreads();
    }
    mx = red[0];
    __syncthreads();

    float sum = 0.f;
#pragma unroll
    for (int i = 0; i < 4; i++) { v[i] = __expf(v[i] - mx); sum += v[i]; }
    red[t] = sum; __syncthreads();
    for (int s = 128; s > 0; s >>= 1) {
        if (t < s) red[t] += red[t + s];
        __syncthreads();
    }
    const float inv = 1.f / red[0];
#pragma unroll
    for (int i = 0; i < 4; i++) p[t + i * 256] = v[i] * inv;
}

// ---------------------------------------------------------------------------
// P @ V: grid (Dm/64, Ss/64, Bb)
// ---------------------------------------------------------------------------
__global__ void k_av()
{
    if (!g_flags[1]) return;
    const float* A  = g_p + (size_t)blockIdx.z * Ss * Ss + (size_t)blockIdx.y * 64 * Ss;
    const float* Bm = g_v + (size_t)blockIdx.z * Ss * Dm + blockIdx.x * 64;

    float acc[4][4] = {};
    gemm_tile<false>(A, Bm, acc, Ss, Ss, Dm);

    const int row = (int)blockIdx.z * Ss + blockIdx.y * 64 + (threadIdx.x >> 4) * 4;
    const int col = blockIdx.x * 64 + (threadIdx.x & 15) * 4;
#pragma unroll
    for (int i = 0; i < 4; i++)
#pragma unroll
        for (int j = 0; j < 4; j++)
            g_ao[(size_t)(row + i) * Dm + col + j] = acc[i][j];
}

// ---------------------------------------------------------------------------
// Output projection: grid (Dm/64, MT/64).  h = ao @ Wo[blk][op]   (full replace)
// ---------------------------------------------------------------------------
__global__ void k_out(float* __restrict__ h, const float* __restrict__ wo, int blk)
{
    if (!g_flags[1]) return;
    const int op = g_flags[0];
    const float* W  = wo + ((size_t)blk * NOPS + op) * Dm * Dm;
    const float* A  = g_ao + (size_t)blockIdx.y * 64 * Dm;
    const float* Bm = W + blockIdx.x * 64;

    float acc[4][4] = {};
    gemm_tile<false>(A, Bm, acc, Dm, Dm, Dm);

    const int row = blockIdx.y * 64 + (threadIdx.x >> 4) * 4;
    const int col = blockIdx.x * 64 + (threadIdx.x & 15) * 4;
#pragma unroll
    for (int i = 0; i < 4; i++)
#pragma unroll
        for (int j = 0; j < 4; j++)
            h[(size_t)(row + i) * Dm + col + j] = acc[i][j];
}

// ---------------------------------------------------------------------------
// FFN layer 1: grid (Hf/64, MT/64).  Z = relu(h @ W1[blk][op] + b1[blk][op])
// ---------------------------------------------------------------------------
__global__ void k_ffn1(const float* __restrict__ h,
                       const float* __restrict__ w1,
                       const float* __restrict__ b1, int blk)
{
    if (!g_flags[2]) return;
    const int op = g_flags[0];
    const float* W  = w1 + ((size_t)blk * NOPS + op) * Dm * Hf;
    const float* bias = b1 + ((size_t)blk * NOPS + op) * Hf;
    const float* A  = h + (size_t)blockIdx.y * 64 * Dm;
    const float* Bm = W + blockIdx.x * 64;

    float acc[4][4] = {};
    gemm_tile<false>(A, Bm, acc, Dm, Dm, Hf);

    const int row = blockIdx.y * 64 + (threadIdx.x >> 4) * 4;
    const int col = blockIdx.x * 64 + (threadIdx.x & 15) * 4;
#pragma unroll
    for (int i = 0; i < 4; i++)
#pragma unroll
        for (int j = 0; j < 4; j++)
            g_z[(size_t)(row + i) * Hf + col + j] = fmaxf(acc[i][j] + bias[col + j], 0.f);
}

// ---------------------------------------------------------------------------
// FFN layer 2: grid (Dm/64, MT/64).  h = Z @ W2[blk][op] + b2[blk][op]
// ---------------------------------------------------------------------------
__global__ void k_ffn2(float* __restrict__ h,
                       const float* __restrict__ w2,
                       const float* __restrict__ b2, int blk)
{
    if (!g_flags[2]) return;
    const int op = g_flags[0];
    const float* W  = w2 + ((size_t)blk * NOPS + op) * Hf * Dm;
    const float* bias = b2 + ((size_t)blk * NOPS + op) * Dm;
    const float* A  = g_z + (size_t)blockIdx.y * 64 * Hf;
    const float* Bm = W + blockIdx.x * 64;

    float acc[4][4] = {};
    gemm_tile<false>(A, Bm, acc, Hf, Hf, Dm);

    const int row = blockIdx.y * 64 + (threadIdx.x >> 4) * 4;
    const int col = blockIdx.x * 64 + (threadIdx.x & 15) * 4;
#pragma unroll
    for (int i = 0; i < 4; i++)
#pragma unroll
        for (int j = 0; j < 4; j++)
            h[(size_t)(row + i) * Dm + col + j] = acc[i][j] + bias[col + j];
}

// ---------------------------------------------------------------------------
// Launch: 33 blocks; per block, data-dependent routing via g_flags gate.
// Graph-capturable: only async memcpy D2D + kernel launches on stream 0.
// ---------------------------------------------------------------------------
extern "C" void kernel_launch(void* const* d_in, const int* in_sizes, int n_in,
                              void* d_out, int out_size)
{
    const float* x  = (const float*)d_in[0];
    const float* w1 = (const float*)d_in[1];
    const float* b1 = (const float*)d_in[2];
    const float* w2 = (const float*)d_in[3];
    const float* b2 = (const float*)d_in[4];
    const float* wq = (const float*)d_in[5];
    const float* wk = (const float*)d_in[6];
    const float* wv = (const float*)d_in[7];
    const float* wo = (const float*)d_in[8];
    float* h = (float*)d_out;

    cudaMemcpyAsync(h, x, (size_t)MT * Dm * sizeof(float),
                    cudaMemcpyDeviceToDevice, 0);

    const dim3 thr(256);
    const dim3 g_qkvd (Dm / 64, MT / 64, 3);
    const dim3 g_scd  (Ss / 64, Ss / 64, Bb);
    const dim3 g_avd  (Dm / 64, Ss / 64, Bb);
    const dim3 g_outd (Dm / 64, MT / 64);
    const dim3 g_f1d  (Hf / 64, MT / 64);
    const dim3 g_f2d  (Dm / 64, MT / 64);

    for (int blk = 0; blk < NBLK; blk++) {
        k_op     <<<1, 1>>>(h, blk);
        k_qkv    <<<g_qkvd, thr>>>(h, wq, wk, wv, blk);
        k_scores <<<g_scd,  thr>>>();
        k_softmax<<<MT,     thr>>>();
        k_av     <<<g_avd,  thr>>>();
        k_out    <<<g_outd, thr>>>(h, wo, blk);
        k_ffn1   <<<g_f1d,  thr>>>(h, w1, b1, blk);
        k_ffn2   <<<g_f2d,  thr>>>(h, w2, b2, blk);
    }
}

// round 4
// speedup vs baseline: 4.0134x; 4.0134x over previous
#include <cuda_runtime.h>

#define NBLK 33
#define NOPS 19
#define Dm   128
#define Hf   512
#define Bb   8
#define Ss   1024
#define MT   (Bb*Ss)
#define GRID 128
#define NTHR 256
#define TS   68      // padded stride for transposed smem tiles

// ---------------------------------------------------------------------------
// Device scratch (static; no runtime alloc)
// ---------------------------------------------------------------------------
__device__ float g_q[(size_t)MT * Dm];
__device__ float g_k[(size_t)MT * Dm];
__device__ float g_v[(size_t)MT * Dm];

// ---------------------------------------------------------------------------
// Routing masks (deterministic _build_masks() logic)
// ---------------------------------------------------------------------------
__device__ __host__ __forceinline__ bool is_carry(int op) {
    return op == 0 || op == 1 || op == 2 || (op >= 10 && op <= 13);
}
__device__ __forceinline__ bool amask(int b, int op) {
    if (b >= 1 && b <= 7) return is_carry(op);
    if (b == 8)           return op == 14 || op == 15 || op == 8 || op == 9;
    if (b == 32)          return op >= 10 && op <= 13;
    return false;
}
__device__ __forceinline__ bool fmask(int b, int op) {
    if (b == 0)              return true;
    if (b >= 1 && b <= 7)    return is_carry(op);
    if (b == 8)              return op == 14 || op == 15 || op == 8 || op == 9;
    if (b >= 16 && b <= 31)  return op == 3 || op == 4;
    if (b == 32)             return op == 5 || op == 6 || op == 7 || op == 2 ||
                                    op == 4 || (op >= 10 && op <= 13);
    return false;
}

// ---------------------------------------------------------------------------
// FMA micro-tiles
// ---------------------------------------------------------------------------
__device__ __forceinline__ void fma48(float (&acc)[4][8], float4 a, float4 b0, float4 b1) {
    float av[4] = {a.x, a.y, a.z, a.w};
    float bv[8] = {b0.x, b0.y, b0.z, b0.w, b1.x, b1.y, b1.z, b1.w};
#pragma unroll
    for (int i = 0; i < 4; i++)
#pragma unroll
        for (int j = 0; j < 8; j++) acc[i][j] += av[i] * bv[j];
}
__device__ __forceinline__ void fma44(float (&acc)[4][4], float4 a, float4 b) {
    float av[4] = {a.x, a.y, a.z, a.w};
    float bv[4] = {b.x, b.y, b.z, b.w};
#pragma unroll
    for (int i = 0; i < 4; i++)
#pragma unroll
        for (int j = 0; j < 4; j++) acc[i][j] += av[i] * bv[j];
}

// C(64x128) += A(64xKK) * Wg(KK x ldw window). A transposed in smem AT[k][r]
// (stride TS). Ws: 16x128 staging, register double-buffered.
template <int KK>
__device__ __forceinline__ void gemmT128(const float* AT, const float* __restrict__ Wg,
                                         int ldw, float* Ws, float (&acc)[4][8]) {
    const int tid = threadIdx.x;
    const int r0 = (tid >> 4) * 4, c0 = (tid & 15) * 8;
    const int sr = tid >> 4, sc = (tid & 15) * 8;
    const float* src0 = Wg + (size_t)sr * ldw + sc;
    float4 ra = *(const float4*)(src0);
    float4 rb = *(const float4*)(src0 + 4);
    for (int k0 = 0; k0 < KK; k0 += 16) {
        __syncthreads();
        *(float4*)&Ws[sr * 128 + sc]     = ra;
        *(float4*)&Ws[sr * 128 + sc + 4] = rb;
        __syncthreads();
        if (k0 + 16 < KK) {
            const float* nsrc = Wg + (size_t)(k0 + 16 + sr) * ldw + sc;
            ra = *(const float4*)(nsrc);
            rb = *(const float4*)(nsrc + 4);
        }
#pragma unroll
        for (int k = 0; k < 16; k++) {
            float4 a  = *(const float4*)&AT[(k0 + k) * TS + r0];
            float4 b0 = *(const float4*)&Ws[k * 128 + c0];
            float4 b1 = *(const float4*)&Ws[k * 128 + c0 + 4];
            fma48(acc, a, b0, b1);
        }
    }
}

// C(64x64) += A(64x128) * Wg(128 x ldw window). Ws: 16x64 staging, reg dbuf.
__device__ __forceinline__ void gemmT64_k128(const float* AT, const float* __restrict__ Wg,
                                             int ldw, float* Ws, float (&acc)[4][4]) {
    const int tid = threadIdx.x;
    const int r0 = (tid >> 4) * 4, c0 = (tid & 15) * 4;
    const int sr = tid >> 4, sc = (tid & 15) * 4;
    float4 ra = *(const float4*)(Wg + (size_t)sr * ldw + sc);
    for (int k0 = 0; k0 < 128; k0 += 16) {
        __syncthreads();
        *(float4*)&Ws[sr * 64 + sc] = ra;
        __syncthreads();
        if (k0 + 16 < 128)
            ra = *(const float4*)(Wg + (size_t)(k0 + 16 + sr) * ldw + sc);
#pragma unroll
        for (int k = 0; k < 16; k++) {
            float4 a = *(const float4*)&AT[(k0 + k) * TS + r0];
            float4 b = *(const float4*)&Ws[k * 64 + c0];
            fma44(acc, a, b);
        }
    }
}

// ---------------------------------------------------------------------------
// Opcode from h[0,0,:NOPS] (first-max argmax, matching jnp.argmax)
// ---------------------------------------------------------------------------
__device__ __forceinline__ int compute_op(const float* __restrict__ h, int* s_op) {
    if (threadIdx.x == 0) {
        float best = h[0]; int bi = 0;
        for (int i = 1; i < NOPS; i++) {
            float v = h[i];
            if (v > best) { best = v; bi = i; }
        }
        *s_op = bi;
    }
    __syncthreads();
    return *s_op;
}

// ---------------------------------------------------------------------------
// Kernel 1: Q/K/V projections -> global (only launched for blocks that can
// have attention; self-gates on the data-dependent op).
// ---------------------------------------------------------------------------
__global__ void __launch_bounds__(NTHR, 1)
k_qkv(int blk, const float* __restrict__ h,
      const float* __restrict__ wq, const float* __restrict__ wk,
      const float* __restrict__ wv)
{
    __shared__ float hT[128 * TS];
    __shared__ float Ws[16 * 128];
    __shared__ int s_op;

    const int op = compute_op(h, &s_op);
    if (!amask(blk, op)) return;

    const int tid = threadIdx.x;
    const int row0 = blockIdx.x * 64;
    const int r0 = (tid >> 4) * 4, c0 = (tid & 15) * 8;
    const size_t woff = ((size_t)blk * NOPS + op) * Dm * Dm;

    for (int i = tid; i < 64 * Dm / 4; i += NTHR) {
        int r = i >> 5, d = (i & 31) * 4;
        float4 v = *(const float4*)&h[(size_t)(row0 + r) * Dm + d];
        hT[(d + 0) * TS + r] = v.x; hT[(d + 1) * TS + r] = v.y;
        hT[(d + 2) * TS + r] = v.z; hT[(d + 3) * TS + r] = v.w;
    }
    __syncthreads();

    const float* Wsrc[3] = {wq + woff, wk + woff, wv + woff};
    float* dst[3] = {g_q, g_k, g_v};
#pragma unroll
    for (int m = 0; m < 3; m++) {
        float acc[4][8] = {};
        gemmT128<128>(hT, Wsrc[m], Dm, Ws, acc);
#pragma unroll
        for (int i = 0; i < 4; i++) {
            float4 t0 = {acc[i][0], acc[i][1], acc[i][2], acc[i][3]};
            float4 t1 = {acc[i][4], acc[i][5], acc[i][6], acc[i][7]};
            *(float4*)&dst[m][(size_t)(row0 + r0 + i) * Dm + c0]     = t0;
            *(float4*)&dst[m][(size_t)(row0 + r0 + i) * Dm + c0 + 4] = t1;
        }
        __syncthreads();   // Ws reuse across m
    }
}

// ---------------------------------------------------------------------------
// Kernel 2: flash attention + output projection + fused FFN (self-gated).
// ---------------------------------------------------------------------------
__global__ void __launch_bounds__(NTHR, 1)
k_blk(int blk, float* __restrict__ h,
      const float* __restrict__ wo,
      const float* __restrict__ w1, const float* __restrict__ b1,
      const float* __restrict__ w2, const float* __restrict__ b2)
{
    extern __shared__ float sm[];
    float* hT = sm;                              // 128*TS
    float* qT = sm + 128 * TS;                   // 128*TS (alias: aoT)
    float* kT = sm + 2 * 128 * TS;               // 128*TS (alias: Ws/W1s/W2s)
    float* vS = sm + 3 * 128 * TS;               // 64*128  (alias: zT)
    float* pT = sm + 3 * 128 * TS + 64 * 128;    // 64*TS
    float* Ws  = kT;
    float* W1s = kT;
    float* W2s = kT + 1024;
    float* zT  = vS;

    __shared__ int s_op;
    const int op = compute_op(h, &s_op);
    const bool act_a = amask(blk, op);
    const bool act_f = fmask(blk, op);
    if (!act_a && !act_f) return;

    const int tid  = threadIdx.x;
    const int tile = blockIdx.x;
    const int row0 = tile * 64;
    const int bb   = (tile >> 4) * Ss;
    const int ty = tid >> 4, tx = tid & 15;
    const int r0 = ty * 4, c0 = tx * 8, c4 = tx * 4;

    bool have_hT = false;

    if (act_a) {
        // ---- load qT (own rows, transposed) ----
        for (int i = tid; i < 64 * Dm / 4; i += NTHR) {
            int r = i >> 5, d = (i & 31) * 4;
            float4 v = *(const float4*)&g_q[(size_t)(row0 + r) * Dm + d];
            qT[(d + 0) * TS + r] = v.x; qT[(d + 1) * TS + r] = v.y;
            qT[(d + 2) * TS + r] = v.z; qT[(d + 3) * TS + r] = v.w;
        }
        __syncthreads();

        // ---- flash attention over 16 k-tiles ----
        float m[4], l[4], o[4][8];
#pragma unroll
        for (int i = 0; i < 4; i++) {
            m[i] = -1e30f; l[i] = 0.f;
#pragma unroll
            for (int j = 0; j < 8; j++) o[i][j] = 0.f;
        }

        for (int kt = 0; kt < 16; kt++) {
            for (int i = tid; i < 64 * Dm; i += NTHR) {
                int kr = i >> 7, d = i & 127;
                size_t gi = (size_t)(bb + kt * 64 + kr) * Dm + d;
                kT[d * TS + kr]  = g_k[gi];
                vS[kr * 128 + d] = g_v[gi];
            }
            __syncthreads();

            float s[4][4] = {};
#pragma unroll 8
            for (int k = 0; k < 128; k++) {
                float4 a = *(const float4*)&qT[k * TS + r0];
                float4 b = *(const float4*)&kT[k * TS + c4];
                fma44(s, a, b);
            }
            const float scale = 0.08838834764831845f;
#pragma unroll
            for (int i = 0; i < 4; i++) {
#pragma unroll
                for (int j = 0; j < 4; j++) s[i][j] *= scale;
                float mx = fmaxf(fmaxf(s[i][0], s[i][1]), fmaxf(s[i][2], s[i][3]));
                mx = fmaxf(mx, __shfl_xor_sync(0xffffffffu, mx, 8, 16));
                mx = fmaxf(mx, __shfl_xor_sync(0xffffffffu, mx, 4, 16));
                mx = fmaxf(mx, __shfl_xor_sync(0xffffffffu, mx, 2, 16));
                mx = fmaxf(mx, __shfl_xor_sync(0xffffffffu, mx, 1, 16));
                float mn   = fmaxf(m[i], mx);
                float corr = __expf(m[i] - mn);
                float rs = 0.f;
#pragma unroll
                for (int j = 0; j < 4; j++) {
                    float p = __expf(s[i][j] - mn);
                    pT[(c4 + j) * TS + r0 + i] = p;
                    rs += p;
                }
                rs += __shfl_xor_sync(0xffffffffu, rs, 8, 16);
                rs += __shfl_xor_sync(0xffffffffu, rs, 4, 16);
                rs += __shfl_xor_sync(0xffffffffu, rs, 2, 16);
                rs += __shfl_xor_sync(0xffffffffu, rs, 1, 16);
                l[i] = l[i] * corr + rs;
                m[i] = mn;
#pragma unroll
                for (int j = 0; j < 8; j++) o[i][j] *= corr;
            }
            __syncthreads();              // pT complete

#pragma unroll 4
            for (int kr = 0; kr < 64; kr++) {
                float4 a  = *(const float4*)&pT[kr * TS + r0];
                float4 b0 = *(const float4*)&vS[kr * 128 + c0];
                float4 b1 = *(const float4*)&vS[kr * 128 + c0 + 4];
                fma48(o, a, b0, b1);
            }
            __syncthreads();              // done with kT/vS/pT
        }

        // normalize -> aoT (aliases qT)
#pragma unroll
        for (int i = 0; i < 4; i++) {
            float inv = 1.f / l[i];
#pragma unroll
            for (int j = 0; j < 8; j++) qT[(c0 + j) * TS + r0 + i] = o[i][j] * inv;
        }
        __syncthreads();

        // ---- output projection ----
        const size_t woff = ((size_t)blk * NOPS + op) * Dm * Dm;
        float acc[4][8] = {};
        gemmT128<128>(qT, wo + woff, Dm, Ws, acc);
        if (act_f) {
            // feed FFN directly through smem (h never touched)
#pragma unroll
            for (int i = 0; i < 4; i++)
#pragma unroll
                for (int j = 0; j < 8; j++)
                    hT[(c0 + j) * TS + r0 + i] = acc[i][j];
            have_hT = true;
        } else {
#pragma unroll
            for (int i = 0; i < 4; i++) {
                float4 t0 = {acc[i][0], acc[i][1], acc[i][2], acc[i][3]};
                float4 t1 = {acc[i][4], acc[i][5], acc[i][6], acc[i][7]};
                *(float4*)&h[(size_t)(row0 + r0 + i) * Dm + c0]     = t0;
                *(float4*)&h[(size_t)(row0 + r0 + i) * Dm + c0 + 4] = t1;
            }
        }
        __syncthreads();
    }

    if (act_f) {
        if (!have_hT) {
            for (int i = tid; i < 64 * Dm / 4; i += NTHR) {
                int r = i >> 5, d = (i & 31) * 4;
                float4 v = *(const float4*)&h[(size_t)(row0 + r) * Dm + d];
                hT[(d + 0) * TS + r] = v.x; hT[(d + 1) * TS + r] = v.y;
                hT[(d + 2) * TS + r] = v.z; hT[(d + 3) * TS + r] = v.w;
            }
            __syncthreads();
        }

        const size_t off1 = ((size_t)blk * NOPS + op) * Dm * Hf;
        const size_t off2 = ((size_t)blk * NOPS + op) * Hf * Dm;
        const float* b1g = b1 + ((size_t)blk * NOPS + op) * Hf;
        const float* b2g = b2 + ((size_t)blk * NOPS + op) * Dm;

        float acc2[4][8] = {};
        for (int ch = 0; ch < 8; ch++) {
            float acc1[4][4] = {};
            gemmT64_k128(hT, w1 + off1 + ch * 64, Hf, W1s, acc1);
            // bias + relu -> zT (transposed)
#pragma unroll
            for (int j = 0; j < 4; j++) {
                float bv = __ldg(&b1g[ch * 64 + c4 + j]);
#pragma unroll
                for (int i = 0; i < 4; i++)
                    zT[(c4 + j) * TS + r0 + i] = fmaxf(acc1[i][j] + bv, 0.f);
            }
            // acc2 += z @ W2[ch*64 : ch*64+64, :]  (reg double-buffered)
            {
                const float* src0 = w2 + off2 + (size_t)(ch * 64 + ty) * Dm + c0;
                float4 ra = *(const float4*)(src0);
                float4 rb = *(const float4*)(src0 + 4);
                for (int k0 = 0; k0 < 64; k0 += 16) {
                    __syncthreads();      // orders zT writes before reads too
                    *(float4*)&W2s[ty * 128 + c0]     = ra;
                    *(float4*)&W2s[ty * 128 + c0 + 4] = rb;
                    __syncthreads();
                    if (k0 + 16 < 64) {
                        const float* nsrc = w2 + off2 +
                            (size_t)(ch * 64 + k0 + 16 + ty) * Dm + c0;
                        ra = *(const float4*)(nsrc);
                        rb = *(const float4*)(nsrc + 4);
                    }
#pragma unroll
                    for (int k = 0; k < 16; k++) {
                        float4 a   = *(const float4*)&zT[(k0 + k) * TS + r0];
                        float4 b0  = *(const float4*)&W2s[k * 128 + c0];
                        float4 b1v = *(const float4*)&W2s[k * 128 + c0 + 4];
                        fma48(acc2, a, b0, b1v);
                    }
                }
            }
            __syncthreads();              // done reading zT before next chunk
        }
        float4 bb0 = *(const float4*)&b2g[c0];
        float4 bb1 = *(const float4*)&b2g[c0 + 4];
#pragma unroll
        for (int i = 0; i < 4; i++) {
            float4 t0 = {acc2[i][0] + bb0.x, acc2[i][1] + bb0.y,
                         acc2[i][2] + bb0.z, acc2[i][3] + bb0.w};
            float4 t1 = {acc2[i][4] + bb1.x, acc2[i][5] + bb1.y,
                         acc2[i][6] + bb1.z, acc2[i][7] + bb1.w};
            *(float4*)&h[(size_t)(row0 + r0 + i) * Dm + c0]     = t0;
            *(float4*)&h[(size_t)(row0 + r0 + i) * Dm + c0 + 4] = t1;
        }
    }
}

// ---------------------------------------------------------------------------
// Copy x -> h
// ---------------------------------------------------------------------------
__global__ void k_copy(const float* __restrict__ x, float* __restrict__ h) {
    size_t i = (size_t)blockIdx.x * blockDim.x + threadIdx.x;
    ((float4*)h)[i] = ((const float4*)x)[i];
}

// ---------------------------------------------------------------------------
// Launch: host-static dead-block elimination; 35 launches total.
// ---------------------------------------------------------------------------
extern "C" void kernel_launch(void* const* d_in, const int* in_sizes, int n_in,
                              void* d_out, int out_size)
{
    const float* x  = (const float*)d_in[0];
    const float* w1 = (const float*)d_in[1];
    const float* b1 = (const float*)d_in[2];
    const float* w2 = (const float*)d_in[3];
    const float* b2 = (const float*)d_in[4];
    const float* wq = (const float*)d_in[5];
    const float* wk = (const float*)d_in[6];
    const float* wv = (const float*)d_in[7];
    const float* wo = (const float*)d_in[8];
    float* h = (float*)d_out;

    const int smem_blk = (3 * 128 * TS + 64 * 128 + 64 * TS) * sizeof(float); // 154,624 B
    cudaFuncSetAttribute(k_blk, cudaFuncAttributeMaxDynamicSharedMemorySize, smem_blk);

    k_copy<<<MT * Dm / 4 / 256, 256>>>(x, h);

    for (int blk = 0; blk < NBLK; blk++) {
        // Static reachability: can ANY op activate attention / ffn at this block?
        const bool anyA = (blk >= 1 && blk <= 8) || blk == 32;
        const bool anyF = (blk == 0) || (blk >= 1 && blk <= 8) ||
                          (blk >= 16 && blk <= 31) || blk == 32;
        if (anyA)
            k_qkv<<<GRID, NTHR>>>(blk, h, wq, wk, wv);
        if (anyA || anyF)
            k_blk<<<GRID, NTHR, smem_blk>>>(blk, h, wo, w1, b1, w2, b2);
    }
}